// round 16
// baseline (speedup 1.0000x reference)
#include <cuda_runtime.h>
#include <cuda_fp16.h>
#include <cstdint>

// ============================================================
// x(16384,128) f32, p(16384,8) f32, W(128,4096) f32, b(4096) f32
// logits[b,n] = sum_f x[b,f]*W[f,n],  n = c*512 + d*64 + r
// out[b, d*64+r] = sum_c p[b,c] * softmax_d(logits[b,c,:,r])
//
// R16: TWO-KERNEL SPLIT.
//  A: pure fp16 mma.sync GEMM (R10 loop, 32 acc chains, no
//     epilogue) -> permuted fp16 logits (n' = r*64 + c*8 + d)
//     in a 128MB device buffer.
//  B: pure softmax: 1M threads, one (b,r) each; 64 logits = one
//     contiguous 128B read, thread-local softmax (no shuffles),
//     coalesced stores. MUFU-bound at high occupancy.
// ============================================================

#define NF 128

// -------- device scratch --------
__device__ __align__(1024) uint8_t g_Wh[32u * 32768];   // [slab*2+kh][256n][8ch][16B]
__device__ __align__(1024) uint8_t g_Xh[128u * 32768];  // [rowblk][128r][16ch][16B]
__device__ __align__(16) float g_biasp[4096];
__device__ __align__(1024) uint32_t g_logits[16384u * 2048u];  // 128 MB fp16 pairs

// -------- kernel A smem --------
#define SM_XH   0                  // 32768
#define SM_W    32768              // 2 slots x 65536 (full slab)
#define SM_TOT  163840

__device__ __forceinline__ uint32_t smem_u32(const void* p) {
    return (uint32_t)__cvta_generic_to_shared(p);
}
__device__ __forceinline__ void cp16(uint32_t dst, const void* src) {
    asm volatile("cp.async.cg.shared.global [%0], [%1], 16;" :: "r"(dst), "l"(src));
}
#define LDSM4(r, a) \
    asm volatile("ldmatrix.sync.aligned.m8n8.x4.shared.b16 {%0,%1,%2,%3}, [%4];" \
        : "=r"((r)[0]), "=r"((r)[1]), "=r"((r)[2]), "=r"((r)[3]) : "r"(a))

__device__ __forceinline__ void mma16816h(float* c, const uint32_t* a,
                                          uint32_t b0, uint32_t b1) {
    asm volatile(
        "mma.sync.aligned.m16n8k16.row.col.f32.f16.f16.f32 "
        "{%0,%1,%2,%3}, {%4,%5,%6,%7}, {%8,%9}, {%0,%1,%2,%3};"
        : "+f"(c[0]), "+f"(c[1]), "+f"(c[2]), "+f"(c[3])
        : "r"(a[0]), "r"(a[1]), "r"(a[2]), "r"(a[3]), "r"(b0), "r"(b1));
}
__device__ __forceinline__ uint32_t pack2h(float a, float b) {
    __half2 h;
    h.x = __float2half_rn(a);
    h.y = __float2half_rn(b);
    return *reinterpret_cast<uint32_t*>(&h);
}

// ============================================================
// Merged prep (unchanged, validated R10-R15)
// ============================================================
__global__ void prep_kernel(const float* __restrict__ X,
                            const float* __restrict__ W,
                            const float* __restrict__ bias) {
    int idx = blockIdx.x * 256 + threadIdx.x;

    if (idx < 4096) {
        int n = idx;
        int c = n >> 9, d = (n >> 6) & 7, r = n & 63;
        g_biasp[r * 64 + c * 8 + d] = bias[n];
    }

    if (idx < 64 * 4096) {
        int f2 = (idx >> 12) * 2;
        int n  = idx & 4095;
        float w0 = W[(size_t)f2 * 4096 + n];
        float w1 = W[(size_t)(f2 + 1) * 4096 + n];
        int c = n >> 9, d = (n >> 6) & 7, r = n & 63;
        int np = r * 64 + c * 8 + d;            // permuted column
        int slab = np >> 8, nl = np & 255;
        int kh = f2 >> 6, kl = f2 & 63;
        int ch = kl >> 3;
        uint32_t off = (uint32_t)(nl * 128 + (((ch ^ (nl & 7)) & 7) << 4) + (kl & 7) * 2);
        *(uint32_t*)(g_Wh + ((size_t)slab * 2 + kh) * 32768 + off) = pack2h(w0, w1);
    }

    {
        int row = idx >> 6;
        int k2  = (idx & 63) * 2;
        float2 v = *reinterpret_cast<const float2*>(X + (size_t)row * NF + k2);
        int blk = row >> 7, rl = row & 127;
        int ch = k2 >> 3;
        uint32_t off = (uint32_t)(rl * 256 + ((ch ^ (rl & 7)) << 4) + (k2 & 7) * 2);
        *(uint32_t*)(g_Xh + (size_t)blk * 32768 + off) = pack2h(v.x, v.y);
    }
}

// ============================================================
// Kernel A: pure GEMM -> fp16 permuted logits.
// 128 CTAs x 256 threads, warp grid 4(m) x 2(n), R10 loop.
// ============================================================
__global__ __launch_bounds__(256, 1)
void gemm_kernel() {
    extern __shared__ __align__(1024) uint8_t smem[];
    const uint32_t sb = smem_u32(smem);

    const int tid = threadIdx.x, lane = tid & 31, warp = tid >> 5;
    const int wm = warp >> 1, wn = warp & 1;    // warp tile 32 x 128
    const int rowbase = blockIdx.x * 128;

    // ---- prologue: X image + W slab 0 ----
    {
        const uint8_t* gx = g_Xh + (size_t)blockIdx.x * 32768;
        #pragma unroll
        for (int i = 0; i < 8; i++) {
            int o = (tid + i * 256) * 16;
            cp16(sb + SM_XH + o, gx + o);
        }
        #pragma unroll
        for (int i = 0; i < 16; i++) {
            int o = (tid + i * 256) * 16;
            cp16(sb + SM_W + o, g_Wh + o);
        }
        asm volatile("cp.async.commit_group;");
    }

    const int arow_base = wm * 32 + (lane & 7) + ((lane >> 3) & 1) * 8;
    const int bn0 = wn * 128 + (lane & 7) + ((lane >> 4) << 3);
    const int q = lane & 3, rowq = lane >> 2;

    float acc[2][16][4];

    for (int j = 0; j < 16; j++) {
        asm volatile("cp.async.wait_group 0;");
        __syncthreads();

        if (j + 1 < 16) {
            const uint8_t* src = g_Wh + (size_t)(j + 1) * 65536;
            uint32_t dst = sb + SM_W + ((j + 1) & 1) * 65536;
            #pragma unroll
            for (int i = 0; i < 16; i++) {
                int o = (tid + i * 256) * 16;
                cp16(dst + o, src + o);
            }
            asm volatile("cp.async.commit_group;");
        }

        #pragma unroll
        for (int mt = 0; mt < 2; mt++)
            #pragma unroll
            for (int nt = 0; nt < 16; nt++)
                #pragma unroll
                for (int e = 0; e < 4; e++) acc[mt][nt][e] = 0.f;

        const uint32_t wslot = sb + SM_W + (j & 1) * 65536;

        #pragma unroll
        for (int kh = 0; kh < 2; kh++) {
            const uint32_t wbase = wslot + kh * 32768;
            #pragma unroll
            for (int ks = 0; ks < 4; ks++) {
                uint32_t ah[2][4];
                const int xch = kh * 8 + ks * 2 + (lane >> 4);
                #pragma unroll
                for (int mt = 0; mt < 2; mt++) {
                    int row = arow_base + mt * 16;
                    uint32_t aoff = (uint32_t)(row * 256 + ((xch ^ (row & 7)) << 4));
                    LDSM4(ah[mt], sb + SM_XH + aoff);
                }
                const int bch = ks * 2 + ((lane >> 3) & 1);
                #pragma unroll
                for (int nb = 0; nb < 2; nb++) {
                    #pragma unroll
                    for (int t2 = 0; t2 < 4; t2++) {
                        uint32_t bh[4];
                        int n = bn0 + nb * 64 + t2 * 16;
                        uint32_t boff = (uint32_t)(n * 128 + (((bch ^ (n & 7)) & 7) << 4));
                        LDSM4(bh, wbase + boff);
                        #pragma unroll
                        for (int mt = 0; mt < 2; mt++)
                            #pragma unroll
                            for (int hf = 0; hf < 2; hf++)
                                mma16816h(acc[mt][nb * 8 + t2 * 2 + hf],
                                          ah[mt], bh[hf * 2], bh[hf * 2 + 1]);
                    }
                }
            }
        }

        // ---- pack fp16 + store permuted logits (no softmax here) ----
        const int nslab = j * 256 + wn * 128;
        #pragma unroll
        for (int mt = 0; mt < 2; mt++) {
            const int rA = wm * 32 + mt * 16 + rowq;
            const size_t row0 = (size_t)(rowbase + rA) * 2048;       // uint32 units
            const size_t row1 = (size_t)(rowbase + rA + 8) * 2048;
            #pragma unroll
            for (int nt = 0; nt < 16; nt++) {
                int colu = ((nslab + nt * 8) >> 1) + q;
                g_logits[row0 + colu] = pack2h(acc[mt][nt][0], acc[mt][nt][1]);
                g_logits[row1 + colu] = pack2h(acc[mt][nt][2], acc[mt][nt][3]);
            }
        }
    }
}

// ============================================================
// Kernel B: pure softmax + p-contraction. 4096 blocks x 256 thr.
// Thread (b, r): reads 64 contiguous fp16 logits (128 B),
// thread-local softmax per c, coalesced output stores.
// ============================================================
__global__ __launch_bounds__(256)
void epi_kernel(const float* __restrict__ p, float* __restrict__ out) {
    __shared__ float biasSm[4096];
    __shared__ float pSm[32];

    const int tid = threadIdx.x;
    const int b0 = blockIdx.x * 4;              // 4 batch rows per block

    #pragma unroll
    for (int i = 0; i < 4; i++)
        ((float4*)biasSm)[tid + i * 256] = ((const float4*)g_biasp)[tid + i * 256];
    if (tid < 32) pSm[tid] = p[(size_t)b0 * 8 + tid];
    __syncthreads();

    const int b = b0 + (tid >> 6);
    const int r = tid & 63;
    const uint4* L4 = (const uint4*)g_logits + ((size_t)b * 512 + r * 8);
    const float* bs = &biasSm[r * 64];
    const float* pc = &pSm[(tid >> 6) * 8];

    float of[8] = {0.f, 0.f, 0.f, 0.f, 0.f, 0.f, 0.f, 0.f};

    #pragma unroll
    for (int c = 0; c < 8; c++) {
        uint4 v = L4[c];
        const __half2* hp = (const __half2*)&v;
        float2 f0 = __half22float2(hp[0]);
        float2 f1 = __half22float2(hp[1]);
        float2 f2 = __half22float2(hp[2]);
        float2 f3 = __half22float2(hp[3]);
        const float* bc = bs + c * 8;
        float e0 = __expf(f0.x + bc[0]);
        float e1 = __expf(f0.y + bc[1]);
        float e2 = __expf(f1.x + bc[2]);
        float e3 = __expf(f1.y + bc[3]);
        float e4 = __expf(f2.x + bc[4]);
        float e5 = __expf(f2.y + bc[5]);
        float e6 = __expf(f3.x + bc[6]);
        float e7 = __expf(f3.y + bc[7]);
        float s = ((e0 + e1) + (e2 + e3)) + ((e4 + e5) + (e6 + e7));
        float f = __fdividef(pc[c], s);
        of[0] = fmaf(e0, f, of[0]);
        of[1] = fmaf(e1, f, of[1]);
        of[2] = fmaf(e2, f, of[2]);
        of[3] = fmaf(e3, f, of[3]);
        of[4] = fmaf(e4, f, of[4]);
        of[5] = fmaf(e5, f, of[5]);
        of[6] = fmaf(e6, f, of[6]);
        of[7] = fmaf(e7, f, of[7]);
    }

    float* ob = out + (size_t)b * 512 + r;
    #pragma unroll
    for (int d = 0; d < 8; d++)
        ob[d * 64] = of[d];
}

// ============================================================
extern "C" void kernel_launch(void* const* d_in, const int* in_sizes, int n_in,
                              void* d_out, int out_size) {
    const float* x    = (const float*)d_in[0];
    const float* p    = (const float*)d_in[1];
    const float* W    = (const float*)d_in[2];
    const float* bias = (const float*)d_in[3];
    float* out = (float*)d_out;

    int B = in_sizes[0] / NF;                    // 16384

    prep_kernel<<<(B * 64) / 256, 256>>>(x, W, bias);

    cudaFuncSetAttribute(gemm_kernel,
                         cudaFuncAttributeMaxDynamicSharedMemorySize, SM_TOT);
    gemm_kernel<<<B / 128, 256, SM_TOT>>>();

    epi_kernel<<<B / 4, 256>>>(p, out);
}

// round 17
// speedup vs baseline: 1.6462x; 1.6462x over previous
#include <cuda_runtime.h>
#include <cuda_fp16.h>
#include <cstdint>

// ============================================================
// x(16384,128) f32, p(16384,8) f32, W(128,4096) f32, b(4096) f32
// logits[b,n] = sum_f x[b,f]*W[f,n],  n = c*512 + d*64 + r
// out[b, d*64+r] = sum_c p[b,c] * softmax_d(logits[b,c,:,r])
//
// R17: single-term fp16 mma.sync (validated R10 numerics),
// columns permuted n' = r*64 + c*8 + d. Re-tiled for occupancy:
// 512 threads / 16 warps (8m x 2n), warp tile 16 x 128 ->
// ~100 regs (<=128 cap) -> 4 warps/SMSP to hide LDSM/HMMA/exp
// latency. R11 group-interleaved epilogue, 1 barrier/slab,
// direct float2 stores (no stage buffer).
// ============================================================

#define NF 128

// -------- device scratch --------
__device__ __align__(1024) uint8_t g_Wh[32u * 32768];   // [slab*2+kh][256n][8ch][16B]
__device__ __align__(1024) uint8_t g_Xh[128u * 32768];  // [rowblk][128r][16ch][16B]
__device__ __align__(16) float g_biasp[4096];

// -------- smem byte offsets --------
#define SM_XH    0                 // 32768
#define SM_W     32768             // 2 slots x 65536 (full slab)
#define SM_BIAS  163840            // 16384
#define SM_P     180224            // 4096
#define SM_TOT   184320

__device__ __forceinline__ uint32_t smem_u32(const void* p) {
    return (uint32_t)__cvta_generic_to_shared(p);
}
__device__ __forceinline__ void cp16(uint32_t dst, const void* src) {
    asm volatile("cp.async.cg.shared.global [%0], [%1], 16;" :: "r"(dst), "l"(src));
}
#define LDSM4(r, a) \
    asm volatile("ldmatrix.sync.aligned.m8n8.x4.shared.b16 {%0,%1,%2,%3}, [%4];" \
        : "=r"((r)[0]), "=r"((r)[1]), "=r"((r)[2]), "=r"((r)[3]) : "r"(a))

__device__ __forceinline__ void mma16816h(float* c, const uint32_t* a,
                                          uint32_t b0, uint32_t b1) {
    asm volatile(
        "mma.sync.aligned.m16n8k16.row.col.f32.f16.f16.f32 "
        "{%0,%1,%2,%3}, {%4,%5,%6,%7}, {%8,%9}, {%0,%1,%2,%3};"
        : "+f"(c[0]), "+f"(c[1]), "+f"(c[2]), "+f"(c[3])
        : "r"(a[0]), "r"(a[1]), "r"(a[2]), "r"(a[3]), "r"(b0), "r"(b1));
}
__device__ __forceinline__ uint32_t pack2h(float a, float b) {
    __half2 h;
    h.x = __float2half_rn(a);
    h.y = __float2half_rn(b);
    return *reinterpret_cast<uint32_t*>(&h);
}

// ============================================================
// Merged prep (unchanged, validated R10-R16)
// ============================================================
__global__ void prep_kernel(const float* __restrict__ X,
                            const float* __restrict__ W,
                            const float* __restrict__ bias) {
    int idx = blockIdx.x * 256 + threadIdx.x;

    if (idx < 4096) {
        int n = idx;
        int c = n >> 9, d = (n >> 6) & 7, r = n & 63;
        g_biasp[r * 64 + c * 8 + d] = bias[n];
    }

    if (idx < 64 * 4096) {
        int f2 = (idx >> 12) * 2;
        int n  = idx & 4095;
        float w0 = W[(size_t)f2 * 4096 + n];
        float w1 = W[(size_t)(f2 + 1) * 4096 + n];
        int c = n >> 9, d = (n >> 6) & 7, r = n & 63;
        int np = r * 64 + c * 8 + d;            // permuted column
        int slab = np >> 8, nl = np & 255;
        int kh = f2 >> 6, kl = f2 & 63;
        int ch = kl >> 3;
        uint32_t off = (uint32_t)(nl * 128 + (((ch ^ (nl & 7)) & 7) << 4) + (kl & 7) * 2);
        *(uint32_t*)(g_Wh + ((size_t)slab * 2 + kh) * 32768 + off) = pack2h(w0, w1);
    }

    {
        int row = idx >> 6;
        int k2  = (idx & 63) * 2;
        float2 v = *reinterpret_cast<const float2*>(X + (size_t)row * NF + k2);
        int blk = row >> 7, rl = row & 127;
        int ch = k2 >> 3;
        uint32_t off = (uint32_t)(rl * 256 + ((ch ^ (rl & 7)) << 4) + (k2 & 7) * 2);
        *(uint32_t*)(g_Xh + (size_t)blk * 32768 + off) = pack2h(v.x, v.y);
    }
}

// ============================================================
// Main kernel: 128 CTAs x 512 threads, warp grid 8(m) x 2(n)
// ============================================================
__global__ __launch_bounds__(512, 1)
void crowds_mma_kernel(const float* __restrict__ p, float* __restrict__ out) {
    extern __shared__ __align__(1024) uint8_t smem[];
    const uint32_t sb = smem_u32(smem);
    const float* biasS = (const float*)(smem + SM_BIAS);
    const float* psS   = (const float*)(smem + SM_P);

    const int tid = threadIdx.x, lane = tid & 31, warp = tid >> 5;
    const int wm = warp >> 1, wn = warp & 1;    // warp tile 16 x 128
    const int rowbase = blockIdx.x * 128;

    // ---- prologue: X image, W slab 0, bias (one group); p transpose ----
    {
        const uint8_t* gx = g_Xh + (size_t)blockIdx.x * 32768;
        #pragma unroll
        for (int i = 0; i < 4; i++) {
            int o = (tid + i * 512) * 16;
            cp16(sb + SM_XH + o, gx + o);
        }
        #pragma unroll
        for (int i = 0; i < 8; i++) {
            int o = (tid + i * 512) * 16;
            cp16(sb + SM_W + o, g_Wh + o);
        }
        #pragma unroll
        for (int i = 0; i < 2; i++) {
            int o = (tid + i * 512) * 16;
            cp16(sb + SM_BIAS + o, (const uint8_t*)g_biasp + o);
        }
        asm volatile("cp.async.commit_group;");
        #pragma unroll
        for (int i = 0; i < 2; i++) {
            int ii = tid + i * 512;
            int row = ii >> 3, c = ii & 7;
            ((float*)(smem + SM_P))[c * 128 + row] = p[(size_t)(rowbase + row) * 8 + c];
        }
    }

    asm volatile("cp.async.wait_group 0;");
    __syncthreads();

    // ---- hoist A fragments (16-row tile, slab-invariant): 32 regs ----
    const int arow = wm * 16 + (lane & 7) + ((lane >> 3) & 1) * 8;
    const int bn0 = wn * 128 + (lane & 7) + ((lane >> 4) << 3);
    const int q = lane & 3, rowq = lane >> 2;

    uint32_t ah[8][4];
    #pragma unroll
    for (int ks8 = 0; ks8 < 8; ks8++) {
        const int xch = ks8 * 2 + (lane >> 4);
        uint32_t aoff = (uint32_t)(arow * 256 + ((xch ^ (arow & 7)) << 4));
        LDSM4(ah[ks8], sb + SM_XH + aoff);
    }

    float accb[2][2][4];   // [buf][hf][4]
    float of[2][4];        // [rb][4]

    for (int j = 0; j < 16; j++) {
        if (j > 0) {
            asm volatile("cp.async.wait_group 0;");
            __syncthreads();
        }

        // prefetch W slab j+1 into other buffer (overlaps slab j work)
        if (j + 1 < 16) {
            const uint8_t* src = g_Wh + (size_t)(j + 1) * 65536;
            uint32_t dst = sb + SM_W + ((j + 1) & 1) * 65536;
            #pragma unroll
            for (int i = 0; i < 8; i++) {
                int o = (tid + i * 512) * 16;
                cp16(dst + o, src + o);
            }
            asm volatile("cp.async.commit_group;");
        }

        #pragma unroll
        for (int rb = 0; rb < 2; rb++)
            #pragma unroll
            for (int e = 0; e < 4; e++) of[rb][e] = 0.f;

        const uint32_t wslot = sb + SM_W + (j & 1) * 65536;

        // ---- 8 groups of 16 cols; MMA(g) then epilogue(g-1) ----
        #pragma unroll
        for (int g = 0; g < 8; g++) {
            #pragma unroll
            for (int hf = 0; hf < 2; hf++)
                #pragma unroll
                for (int e = 0; e < 4; e++) accb[g & 1][hf][e] = 0.f;

            const int n = bn0 + g * 16;
            #pragma unroll
            for (int ks8 = 0; ks8 < 8; ks8++) {
                uint32_t bh[4];
                const int bch = (ks8 & 3) * 2 + ((lane >> 3) & 1);
                uint32_t boff = (uint32_t)((ks8 >> 2) * 32768 + n * 128
                                           + (((bch ^ (n & 7)) & 7) << 4));
                LDSM4(bh, wslot + boff);
                mma16816h(&accb[g & 1][0][0], ah[ks8], bh[0], bh[1]);
                mma16816h(&accb[g & 1][1][0], ah[ks8], bh[2], bh[3]);
            }

            // epilogue of previous group while this group's HMMAs fly
            if (g > 0) {
                const int pg = g - 1, rb = pg >> 2;
                const int row0 = wm * 16 + rowq;
                #pragma unroll
                for (int hf = 0; hf < 2; hf++) {
                    const int c = (pg & 3) * 2 + hf;
                    float2 bv = *(const float2*)&biasS[j * 256 + wn * 128
                                                       + pg * 16 + hf * 8 + q * 2];
                    const float* a4 = &accb[pg & 1][hf][0];
                    float e0 = __expf(a4[0] + bv.x);
                    float e1 = __expf(a4[1] + bv.y);
                    float e2 = __expf(a4[2] + bv.x);
                    float e3 = __expf(a4[3] + bv.y);
                    float s0 = e0 + e1, s1 = e2 + e3;
                    s0 += __shfl_xor_sync(0xffffffffu, s0, 1);
                    s0 += __shfl_xor_sync(0xffffffffu, s0, 2);
                    s1 += __shfl_xor_sync(0xffffffffu, s1, 1);
                    s1 += __shfl_xor_sync(0xffffffffu, s1, 2);
                    float f0 = __fdividef(psS[c * 128 + row0], s0);
                    float f1 = __fdividef(psS[c * 128 + row0 + 8], s1);
                    of[rb][0] = fmaf(e0, f0, of[rb][0]);
                    of[rb][1] = fmaf(e1, f0, of[rb][1]);
                    of[rb][2] = fmaf(e2, f1, of[rb][2]);
                    of[rb][3] = fmaf(e3, f1, of[rb][3]);
                }
            }
        }

        // last group epilogue
        {
            const int pg = 7, rb = 1;
            const int row0 = wm * 16 + rowq;
            #pragma unroll
            for (int hf = 0; hf < 2; hf++) {
                const int c = (pg & 3) * 2 + hf;
                float2 bv = *(const float2*)&biasS[j * 256 + wn * 128
                                                   + pg * 16 + hf * 8 + q * 2];
                const float* a4 = &accb[pg & 1][hf][0];
                float e0 = __expf(a4[0] + bv.x);
                float e1 = __expf(a4[1] + bv.y);
                float e2 = __expf(a4[2] + bv.x);
                float e3 = __expf(a4[3] + bv.y);
                float s0 = e0 + e1, s1 = e2 + e3;
                s0 += __shfl_xor_sync(0xffffffffu, s0, 1);
                s0 += __shfl_xor_sync(0xffffffffu, s0, 2);
                s1 += __shfl_xor_sync(0xffffffffu, s1, 1);
                s1 += __shfl_xor_sync(0xffffffffu, s1, 2);
                float f0 = __fdividef(psS[c * 128 + row0], s0);
                float f1 = __fdividef(psS[c * 128 + row0 + 8], s1);
                of[rb][0] = fmaf(e0, f0, of[rb][0]);
                of[rb][1] = fmaf(e1, f0, of[rb][1]);
                of[rb][2] = fmaf(e2, f1, of[rb][2]);
                of[rb][3] = fmaf(e3, f1, of[rb][3]);
            }
        }

        // ---- direct float2 stores: r = j*4 + wn*2 + rb (rb contiguous) ----
        {
            const int rA = rowbase + wm * 16 + rowq;
            float* b0 = out + (size_t)rA * 512 + (2 * q) * 64 + j * 4 + wn * 2;
            *(float2*)(b0)                = make_float2(of[0][0], of[1][0]);
            *(float2*)(b0 + 64)           = make_float2(of[0][1], of[1][1]);
            *(float2*)(b0 + 8 * 512)      = make_float2(of[0][2], of[1][2]);
            *(float2*)(b0 + 8 * 512 + 64) = make_float2(of[0][3], of[1][3]);
        }
    }
}

// ============================================================
extern "C" void kernel_launch(void* const* d_in, const int* in_sizes, int n_in,
                              void* d_out, int out_size) {
    const float* x    = (const float*)d_in[0];
    const float* p    = (const float*)d_in[1];
    const float* W    = (const float*)d_in[2];
    const float* bias = (const float*)d_in[3];
    float* out = (float*)d_out;

    int B = in_sizes[0] / NF;                    // 16384

    prep_kernel<<<(B * 64) / 256, 256>>>(x, W, bias);

    cudaFuncSetAttribute(crowds_mma_kernel,
                         cudaFuncAttributeMaxDynamicSharedMemorySize, SM_TOT);
    crowds_mma_kernel<<<B / 128, 512, SM_TOT>>>(p, out);
}